// round 7
// baseline (speedup 1.0000x reference)
#include <cuda_runtime.h>

#define NPIX 4096
#define BT 2

// 50*log2(e), log2(e)
#define C50F   72.13475204444817f
#define CL2E   1.4426950408889634f

// ---------------------------------------------------------------------------
// Scratch (device globals)
// ---------------------------------------------------------------------------
__device__ float4 g_u4 [BT][NPIX];            // (u0,u1,u2,-)
__device__ float4 g_iA [BT][NPIX];            // (a0,a1,a2,|a|^2)
__device__ float4 g_iF [BT][NPIX];            // (fs0,fs1,fs2, cLrow = cM + log2 Srow)
__device__ float4 g_jU [BT][NPIX];            // (u0,u1,u2, LSEcol2)
__device__ float4 g_jT [BT][NPIX];            // (ft*log2e x3, -)
__device__ float4 g_jS [BT][NPIX];            // (fs x3, -)

// ---------------------------------------------------------------------------
__device__ __forceinline__ float ex2f(float x) {
    float y; asm("ex2.approx.ftz.f32 %0, %1;" : "=f"(y) : "f"(x)); return y;
}
__device__ __forceinline__ float sqapx(float x) {
    float y; asm("sqrt.approx.ftz.f32 %0, %1;" : "=f"(y) : "f"(x)); return y;
}
__device__ __forceinline__ float wsumf(float v) {
    #pragma unroll
    for (int o = 16; o; o >>= 1) v += __shfl_xor_sync(0xffffffffu, v, o);
    return v;
}
__device__ __forceinline__ float wminf(float v) {
    #pragma unroll
    for (int o = 16; o; o >>= 1) v = fminf(v, __shfl_xor_sync(0xffffffffu, v, o));
    return v;
}

// ---------------------------------------------------------------------------
// Precompute per-i / per-j records (double precision geometry), parallel.
// ---------------------------------------------------------------------------
__global__ void k_pre(const float* __restrict__ f_tar, const float* __restrict__ f_src,
                      const float* __restrict__ Km, const float* __restrict__ Rm,
                      const float* __restrict__ tv) {
    int b = blockIdx.x;
    double Kd[9], Rd[9], td[3];
    #pragma unroll
    for (int m = 0; m < 9; m++) { Kd[m] = (double)Km[b*9+m]; Rd[m] = (double)Rm[b*9+m]; }
    #pragma unroll
    for (int m = 0; m < 3; m++) td[m] = (double)tv[b*3+m];

    double c00 = Kd[4]*Kd[8] - Kd[5]*Kd[7];
    double c10 = Kd[5]*Kd[6] - Kd[3]*Kd[8];
    double c20 = Kd[3]*Kd[7] - Kd[4]*Kd[6];
    double det = Kd[0]*c00 + Kd[1]*c10 + Kd[2]*c20;
    double id  = 1.0 / det;
    double Ki[9];
    Ki[0] = c00*id; Ki[1] = (Kd[2]*Kd[7]-Kd[1]*Kd[8])*id; Ki[2] = (Kd[1]*Kd[5]-Kd[2]*Kd[4])*id;
    Ki[3] = c10*id; Ki[4] = (Kd[0]*Kd[8]-Kd[2]*Kd[6])*id; Ki[5] = (Kd[2]*Kd[3]-Kd[0]*Kd[5])*id;
    Ki[6] = c20*id; Ki[7] = (Kd[1]*Kd[6]-Kd[0]*Kd[7])*id; Ki[8] = (Kd[0]*Kd[4]-Kd[1]*Kd[3])*id;

    double o0 = Kd[0]*td[0] + Kd[1]*td[1] + Kd[2]*td[2];
    double o1 = Kd[3]*td[0] + Kd[4]*td[1] + Kd[5]*td[2];
    double o2 = Kd[6]*td[0] + Kd[7]*td[1] + Kd[8]*td[2];
    float of0 = (float)o0, of1 = (float)o1, of2 = (float)o2;

    const float* fs = f_src + b*3*NPIX;
    const float* ft = f_tar + b*3*NPIX;

    int j = blockIdx.y * 256 + threadIdx.x;
    {
        double px = (double)(j >> 6), py = (double)(j & 63);
        double ca = Ki[0]*px + Ki[1]*py + Ki[2];
        double cb = Ki[3]*px + Ki[4]*py + Ki[5];
        double cc = Ki[6]*px + Ki[7]*py + Ki[8];
        double ra = Rd[0]*ca + Rd[1]*cb + Rd[2]*cc + td[0];
        double rb = Rd[3]*ca + Rd[4]*cb + Rd[5]*cc + td[1];
        double rc = Rd[6]*ca + Rd[7]*cb + Rd[8]*cc + td[2];
        double da = Kd[0]*ra + Kd[1]*rb + Kd[2]*rc - o0;
        double db = Kd[3]*ra + Kd[4]*rb + Kd[5]*rc - o1;
        double dc = Kd[6]*ra + Kd[7]*rb + Kd[8]*rc - o2;
        double inv = 1.0 / sqrt(da*da + db*db + dc*dc);
        float u0 = (float)(da*inv), u1 = (float)(db*inv), u2 = (float)(dc*inv);

        float t0 = ft[j], t1 = ft[NPIX + j], t2 = ft[2*NPIX + j];
        float s0 = fs[j], s1 = fs[NPIX + j], s2 = fs[2*NPIX + j];
        g_u4[b][j] = make_float4(u0, u1, u2, 0.f);
        g_jU[b][j] = make_float4(u0, u1, u2, 0.f);
        g_jT[b][j] = make_float4(t0*CL2E, t1*CL2E, t2*CL2E, 0.f);
        g_jS[b][j] = make_float4(s0, s1, s2, 0.f);

        float a0 = s0 - of0, a1 = s1 - of1, a2 = s2 - of2;
        float na2 = (float)((double)a0*a0 + (double)a1*a1 + (double)a2*a2);
        g_iA[b][j] = make_float4(a0, a1, a2, na2);
        g_iF[b][j] = make_float4(s0, s1, s2, 0.f);
    }
}

// ---------------------------------------------------------------------------
// rowstats: 16 rows/block. Warp = 4 rows (w&3) x j-half (w>>2, 2048 each).
// ---------------------------------------------------------------------------
__global__ void __launch_bounds__(256, 4) k_rowstats() {
    __shared__ float sMin[2][16], sSum[2][16];
    int b = blockIdx.x;
    int lane = threadIdx.x & 31, w = threadIdx.x >> 5;
    int half = w >> 2;
    int rloc = (w & 3) * 4;
    int rbase = blockIdx.y * 16 + rloc;
    float4 A0 = g_iA[b][rbase+0], A1 = g_iA[b][rbase+1];
    float4 A2 = g_iA[b][rbase+2], A3 = g_iA[b][rbase+3];
    const float4* PU = &g_u4[b][half * 2048];

    float m0 = 3.4e38f, m1 = 3.4e38f, m2 = 3.4e38f, m3 = 3.4e38f;
    #pragma unroll 2
    for (int k = lane; k < 2048; k += 32) {
        float4 U = __ldg(PU + k);
        float d0 = fmaf(A0.x, U.x, fmaf(A0.y, U.y, A0.z * U.z)); m0 = fminf(m0, d0*d0);
        float d1 = fmaf(A1.x, U.x, fmaf(A1.y, U.y, A1.z * U.z)); m1 = fminf(m1, d1*d1);
        float d2 = fmaf(A2.x, U.x, fmaf(A2.y, U.y, A2.z * U.z)); m2 = fminf(m2, d2*d2);
        float d3 = fmaf(A3.x, U.x, fmaf(A3.y, U.y, A3.z * U.z)); m3 = fminf(m3, d3*d3);
    }
    m0 = wminf(m0); m1 = wminf(m1); m2 = wminf(m2); m3 = wminf(m3);
    if (lane == 0) {
        sMin[half][rloc+0] = m0; sMin[half][rloc+1] = m1;
        sMin[half][rloc+2] = m2; sMin[half][rloc+3] = m3;
    }
    __syncthreads();
    float cM0 = sqapx(fmaxf(A0.w - fminf(sMin[0][rloc+0], sMin[1][rloc+0]), 0.f)) * C50F;
    float cM1 = sqapx(fmaxf(A1.w - fminf(sMin[0][rloc+1], sMin[1][rloc+1]), 0.f)) * C50F;
    float cM2 = sqapx(fmaxf(A2.w - fminf(sMin[0][rloc+2], sMin[1][rloc+2]), 0.f)) * C50F;
    float cM3 = sqapx(fmaxf(A3.w - fminf(sMin[0][rloc+3], sMin[1][rloc+3]), 0.f)) * C50F;

    float s0 = 0.f, s1 = 0.f, s2 = 0.f, s3 = 0.f;
    for (int k = lane; k < 2048; k += 32) {
        float4 U = __ldg(PU + k);
        float d0 = fmaf(A0.x, U.x, fmaf(A0.y, U.y, A0.z * U.z));
        s0 += ex2f(fmaf(sqapx(fmaxf(fmaf(-d0, d0, A0.w), 0.f)), C50F, -cM0));
        float d1 = fmaf(A1.x, U.x, fmaf(A1.y, U.y, A1.z * U.z));
        s1 += ex2f(fmaf(sqapx(fmaxf(fmaf(-d1, d1, A1.w), 0.f)), C50F, -cM1));
        float d2 = fmaf(A2.x, U.x, fmaf(A2.y, U.y, A2.z * U.z));
        s2 += ex2f(fmaf(sqapx(fmaxf(fmaf(-d2, d2, A2.w), 0.f)), C50F, -cM2));
        float d3 = fmaf(A3.x, U.x, fmaf(A3.y, U.y, A3.z * U.z));
        s3 += ex2f(fmaf(sqapx(fmaxf(fmaf(-d3, d3, A3.w), 0.f)), C50F, -cM3));
    }
    s0 = wsumf(s0); s1 = wsumf(s1); s2 = wsumf(s2); s3 = wsumf(s3);
    if (lane == 0) {
        sSum[half][rloc+0] = s0; sSum[half][rloc+1] = s1;
        sSum[half][rloc+2] = s2; sSum[half][rloc+3] = s3;
    }
    __syncthreads();
    if (threadIdx.x < 16) {
        int r = threadIdx.x;
        int row = blockIdx.y * 16 + r;
        float m = fminf(sMin[0][r], sMin[1][r]);
        float cM = sqapx(fmaxf(g_iA[b][row].w - m, 0.f)) * C50F;
        float S = sSum[0][r] + sSum[1][r];
        ((float*)&g_iF[b][row])[3] = cM + log2f(S);   // cLrow
    }
}

// ---------------------------------------------------------------------------
// col: 16 cols/block. Warp = 4 cols (w&3) x i-half (w>>2). -> LSEcol2.
// ---------------------------------------------------------------------------
__global__ void __launch_bounds__(256, 4) k_col() {
    __shared__ float sSum[2][16];
    int b = blockIdx.x;
    int lane = threadIdx.x & 31, w = threadIdx.x >> 5;
    int half = w >> 2;
    int cloc = (w & 3) * 4;
    int cbase = blockIdx.y * 16 + cloc;
    float4 U0 = g_jU[b][cbase+0], U1 = g_jU[b][cbase+1];
    float4 U2 = g_jU[b][cbase+2], U3 = g_jU[b][cbase+3];
    float4 T0 = g_jT[b][cbase+0], T1 = g_jT[b][cbase+1];
    float4 T2 = g_jT[b][cbase+2], T3 = g_jT[b][cbase+3];
    const float4* PA = &g_iA[b][half * 2048];
    const float4* PF = &g_iF[b][half * 2048];

    float c0 = 0.f, c1 = 0.f, c2 = 0.f, c3 = 0.f;
    for (int k = lane; k < 2048; k += 32) {
        float4 A = __ldg(PA + k);
        float4 F = __ldg(PF + k);
        float nL = -F.w;
        float d0 = fmaf(A.x, U0.x, fmaf(A.y, U0.y, A.z * U0.z));
        float e0 = ex2f(fmaf(sqapx(fmaxf(fmaf(-d0, d0, A.w), 0.f)), C50F, nL));
        float a0 = fmaf(F.x, T0.x, fmaf(F.y, T0.y, F.z * T0.z));
        c0 += ex2f(fmaf(-a0, e0, a0));
        float d1 = fmaf(A.x, U1.x, fmaf(A.y, U1.y, A.z * U1.z));
        float e1 = ex2f(fmaf(sqapx(fmaxf(fmaf(-d1, d1, A.w), 0.f)), C50F, nL));
        float a1 = fmaf(F.x, T1.x, fmaf(F.y, T1.y, F.z * T1.z));
        c1 += ex2f(fmaf(-a1, e1, a1));
        float d2 = fmaf(A.x, U2.x, fmaf(A.y, U2.y, A.z * U2.z));
        float e2 = ex2f(fmaf(sqapx(fmaxf(fmaf(-d2, d2, A.w), 0.f)), C50F, nL));
        float a2 = fmaf(F.x, T2.x, fmaf(F.y, T2.y, F.z * T2.z));
        c2 += ex2f(fmaf(-a2, e2, a2));
        float d3 = fmaf(A.x, U3.x, fmaf(A.y, U3.y, A.z * U3.z));
        float e3 = ex2f(fmaf(sqapx(fmaxf(fmaf(-d3, d3, A.w), 0.f)), C50F, nL));
        float a3 = fmaf(F.x, T3.x, fmaf(F.y, T3.y, F.z * T3.z));
        c3 += ex2f(fmaf(-a3, e3, a3));
    }
    c0 = wsumf(c0); c1 = wsumf(c1); c2 = wsumf(c2); c3 = wsumf(c3);
    if (lane == 0) {
        sSum[half][cloc+0] = c0; sSum[half][cloc+1] = c1;
        sSum[half][cloc+2] = c2; sSum[half][cloc+3] = c3;
    }
    __syncthreads();
    if (threadIdx.x < 16) {
        int c = threadIdx.x;
        int col = blockIdx.y * 16 + c;
        float S = sSum[0][c] + sSum[1][c];
        ((float*)&g_jU[b][col])[3] = log2f(S);        // LSEcol2
    }
}

// ---------------------------------------------------------------------------
// out: 16 rows/block. Warp = 4 rows (w&3) x j-half (w>>2). -> out (B,N,C).
// launch_bounds(256,3): ~84-reg budget so the 4-row state does NOT spill.
// ---------------------------------------------------------------------------
__global__ void __launch_bounds__(256, 3) k_out(float* __restrict__ out) {
    __shared__ float sO[2][16][3];
    int b = blockIdx.x;
    int lane = threadIdx.x & 31, w = threadIdx.x >> 5;
    int half = w >> 2;
    int rloc = (w & 3) * 4;
    int rbase = blockIdx.y * 16 + rloc;
    float4 A0 = g_iA[b][rbase+0], A1 = g_iA[b][rbase+1];
    float4 A2 = g_iA[b][rbase+2], A3 = g_iA[b][rbase+3];
    float4 F0 = g_iF[b][rbase+0], F1 = g_iF[b][rbase+1];
    float4 F2 = g_iF[b][rbase+2], F3 = g_iF[b][rbase+3];
    float nL0 = -F0.w, nL1 = -F1.w, nL2 = -F2.w, nL3 = -F3.w;
    const float4* PU = &g_jU[b][half * 2048];
    const float4* PT = &g_jT[b][half * 2048];
    const float4* PS = &g_jS[b][half * 2048];

    float x0=0,y0=0,z0=0, x1=0,y1=0,z1=0, x2=0,y2=0,z2=0, x3=0,y3=0,z3=0;
    for (int k = lane; k < 2048; k += 32) {
        float4 U = __ldg(PU + k);
        float4 T = __ldg(PT + k);
        float4 S = __ldg(PS + k);
        float d0 = fmaf(A0.x, U.x, fmaf(A0.y, U.y, A0.z * U.z));
        float e0 = ex2f(fmaf(sqapx(fmaxf(fmaf(-d0, d0, A0.w), 0.f)), C50F, nL0));
        float a0 = fmaf(F0.x, T.x, fmaf(F0.y, T.y, F0.z * T.z));
        float p0 = ex2f(fmaf(-a0, e0, a0 - U.w));
        x0 = fmaf(p0, S.x, x0); y0 = fmaf(p0, S.y, y0); z0 = fmaf(p0, S.z, z0);
        float d1 = fmaf(A1.x, U.x, fmaf(A1.y, U.y, A1.z * U.z));
        float e1 = ex2f(fmaf(sqapx(fmaxf(fmaf(-d1, d1, A1.w), 0.f)), C50F, nL1));
        float a1 = fmaf(F1.x, T.x, fmaf(F1.y, T.y, F1.z * T.z));
        float p1 = ex2f(fmaf(-a1, e1, a1 - U.w));
        x1 = fmaf(p1, S.x, x1); y1 = fmaf(p1, S.y, y1); z1 = fmaf(p1, S.z, z1);
        float d2 = fmaf(A2.x, U.x, fmaf(A2.y, U.y, A2.z * U.z));
        float e2 = ex2f(fmaf(sqapx(fmaxf(fmaf(-d2, d2, A2.w), 0.f)), C50F, nL2));
        float a2 = fmaf(F2.x, T.x, fmaf(F2.y, T.y, F2.z * T.z));
        float p2 = ex2f(fmaf(-a2, e2, a2 - U.w));
        x2 = fmaf(p2, S.x, x2); y2 = fmaf(p2, S.y, y2); z2 = fmaf(p2, S.z, z2);
        float d3 = fmaf(A3.x, U.x, fmaf(A3.y, U.y, A3.z * U.z));
        float e3 = ex2f(fmaf(sqapx(fmaxf(fmaf(-d3, d3, A3.w), 0.f)), C50F, nL3));
        float a3 = fmaf(F3.x, T.x, fmaf(F3.y, T.y, F3.z * T.z));
        float p3 = ex2f(fmaf(-a3, e3, a3 - U.w));
        x3 = fmaf(p3, S.x, x3); y3 = fmaf(p3, S.y, y3); z3 = fmaf(p3, S.z, z3);
    }
    x0 = wsumf(x0); y0 = wsumf(y0); z0 = wsumf(z0);
    x1 = wsumf(x1); y1 = wsumf(y1); z1 = wsumf(z1);
    x2 = wsumf(x2); y2 = wsumf(y2); z2 = wsumf(z2);
    x3 = wsumf(x3); y3 = wsumf(y3); z3 = wsumf(z3);
    if (lane == 0) {
        sO[half][rloc+0][0] = x0; sO[half][rloc+0][1] = y0; sO[half][rloc+0][2] = z0;
        sO[half][rloc+1][0] = x1; sO[half][rloc+1][1] = y1; sO[half][rloc+1][2] = z1;
        sO[half][rloc+2][0] = x2; sO[half][rloc+2][1] = y2; sO[half][rloc+2][2] = z2;
        sO[half][rloc+3][0] = x3; sO[half][rloc+3][1] = y3; sO[half][rloc+3][2] = z3;
    }
    __syncthreads();
    if (threadIdx.x < 16) {
        int r = threadIdx.x;
        int row = blockIdx.y * 16 + r;
        int base = b * NPIX * 3 + row * 3;
        out[base]     = sO[0][r][0] + sO[1][r][0];
        out[base + 1] = sO[0][r][1] + sO[1][r][1];
        out[base + 2] = sO[0][r][2] + sO[1][r][2];
    }
}

// ---------------------------------------------------------------------------
extern "C" void kernel_launch(void* const* d_in, const int* in_sizes, int n_in,
                              void* d_out, int out_size) {
    const float* f_tar = (const float*)d_in[0];
    const float* f_src = (const float*)d_in[1];
    const float* Km    = (const float*)d_in[2];
    const float* Rm    = (const float*)d_in[3];
    const float* tv    = (const float*)d_in[4];
    float* out = (float*)d_out;

    dim3 gridN2(BT, NPIX/16);
    k_pre     <<<dim3(BT, 16), 256>>>(f_tar, f_src, Km, Rm, tv);
    k_rowstats<<<gridN2, 256>>>();
    k_col     <<<gridN2, 256>>>();
    k_out     <<<gridN2, 256>>>(out);
}

// round 8
// speedup vs baseline: 1.1001x; 1.1001x over previous
#include <cuda_runtime.h>

#define NPIX 4096
#define BT 2

// 50*log2(e), log2(e)
#define C50F   72.13475204444817f
#define CL2E   1.4426950408889634f

// ---------------------------------------------------------------------------
// Scratch (device globals)
// ---------------------------------------------------------------------------
__device__ float4 g_u4 [BT][NPIX];            // (u0,u1,u2,-)
__device__ float4 g_iA [BT][NPIX];            // (a0,a1,a2,|a|^2)   a = fs - o
__device__ float  g_cL [BT][NPIX];            // cLrow = cM + log2 Srow
__device__ float4 g_jU [BT][NPIX];            // (u0,u1,u2, LSEcol2)
__device__ float4 g_jT [BT][NPIX];            // (ft*log2e x3, o.(ft*log2e))
__device__ float4 g_jS [BT][NPIX];            // (fs x3, -)

// ---------------------------------------------------------------------------
__device__ __forceinline__ float ex2f(float x) {
    float y; asm("ex2.approx.ftz.f32 %0, %1;" : "=f"(y) : "f"(x)); return y;
}
__device__ __forceinline__ float sqapx(float x) {
    float y; asm("sqrt.approx.ftz.f32 %0, %1;" : "=f"(y) : "f"(x)); return y;
}
__device__ __forceinline__ float wsumf(float v) {
    #pragma unroll
    for (int o = 16; o; o >>= 1) v += __shfl_xor_sync(0xffffffffu, v, o);
    return v;
}
__device__ __forceinline__ float wminf(float v) {
    #pragma unroll
    for (int o = 16; o; o >>= 1) v = fminf(v, __shfl_xor_sync(0xffffffffu, v, o));
    return v;
}

// ---------------------------------------------------------------------------
// Precompute per-i / per-j records (double precision geometry), parallel.
// ---------------------------------------------------------------------------
__global__ void k_pre(const float* __restrict__ f_tar, const float* __restrict__ f_src,
                      const float* __restrict__ Km, const float* __restrict__ Rm,
                      const float* __restrict__ tv) {
    int b = blockIdx.x;
    double Kd[9], Rd[9], td[3];
    #pragma unroll
    for (int m = 0; m < 9; m++) { Kd[m] = (double)Km[b*9+m]; Rd[m] = (double)Rm[b*9+m]; }
    #pragma unroll
    for (int m = 0; m < 3; m++) td[m] = (double)tv[b*3+m];

    double c00 = Kd[4]*Kd[8] - Kd[5]*Kd[7];
    double c10 = Kd[5]*Kd[6] - Kd[3]*Kd[8];
    double c20 = Kd[3]*Kd[7] - Kd[4]*Kd[6];
    double det = Kd[0]*c00 + Kd[1]*c10 + Kd[2]*c20;
    double id  = 1.0 / det;
    double Ki[9];
    Ki[0] = c00*id; Ki[1] = (Kd[2]*Kd[7]-Kd[1]*Kd[8])*id; Ki[2] = (Kd[1]*Kd[5]-Kd[2]*Kd[4])*id;
    Ki[3] = c10*id; Ki[4] = (Kd[0]*Kd[8]-Kd[2]*Kd[6])*id; Ki[5] = (Kd[2]*Kd[3]-Kd[0]*Kd[5])*id;
    Ki[6] = c20*id; Ki[7] = (Kd[1]*Kd[6]-Kd[0]*Kd[7])*id; Ki[8] = (Kd[0]*Kd[4]-Kd[1]*Kd[3])*id;

    double o0 = Kd[0]*td[0] + Kd[1]*td[1] + Kd[2]*td[2];
    double o1 = Kd[3]*td[0] + Kd[4]*td[1] + Kd[5]*td[2];
    double o2 = Kd[6]*td[0] + Kd[7]*td[1] + Kd[8]*td[2];
    float of0 = (float)o0, of1 = (float)o1, of2 = (float)o2;

    const float* fs = f_src + b*3*NPIX;
    const float* ft = f_tar + b*3*NPIX;

    int j = blockIdx.y * 256 + threadIdx.x;
    {
        double px = (double)(j >> 6), py = (double)(j & 63);
        double ca = Ki[0]*px + Ki[1]*py + Ki[2];
        double cb = Ki[3]*px + Ki[4]*py + Ki[5];
        double cc = Ki[6]*px + Ki[7]*py + Ki[8];
        double ra = Rd[0]*ca + Rd[1]*cb + Rd[2]*cc + td[0];
        double rb = Rd[3]*ca + Rd[4]*cb + Rd[5]*cc + td[1];
        double rc = Rd[6]*ca + Rd[7]*cb + Rd[8]*cc + td[2];
        double da = Kd[0]*ra + Kd[1]*rb + Kd[2]*rc - o0;
        double db = Kd[3]*ra + Kd[4]*rb + Kd[5]*rc - o1;
        double dc = Kd[6]*ra + Kd[7]*rb + Kd[8]*rc - o2;
        double inv = 1.0 / sqrt(da*da + db*db + dc*dc);
        float u0 = (float)(da*inv), u1 = (float)(db*inv), u2 = (float)(dc*inv);

        float t0 = ft[j]*CL2E, t1 = ft[NPIX + j]*CL2E, t2 = ft[2*NPIX + j]*CL2E;
        float s0 = fs[j], s1 = fs[NPIX + j], s2 = fs[2*NPIX + j];
        float oT = of0*t0 + of1*t1 + of2*t2;          // o . (ft*log2e)
        g_u4[b][j] = make_float4(u0, u1, u2, 0.f);
        g_jU[b][j] = make_float4(u0, u1, u2, 0.f);
        g_jT[b][j] = make_float4(t0, t1, t2, oT);
        g_jS[b][j] = make_float4(s0, s1, s2, 0.f);

        float a0 = s0 - of0, a1 = s1 - of1, a2 = s2 - of2;
        float na2 = (float)((double)a0*a0 + (double)a1*a1 + (double)a2*a2);
        g_iA[b][j] = make_float4(a0, a1, a2, na2);
    }
}

// ---------------------------------------------------------------------------
// rowstats: 16 rows/block. Warp = 4 rows (w&3) x j-half (w>>2, 2048 each).
// Writes g_cL[row] = cM + log2(Srow).
// ---------------------------------------------------------------------------
__global__ void __launch_bounds__(256, 4) k_rowstats() {
    __shared__ float sMin[2][16], sSum[2][16];
    int b = blockIdx.x;
    int lane = threadIdx.x & 31, w = threadIdx.x >> 5;
    int half = w >> 2;
    int rloc = (w & 3) * 4;
    int rbase = blockIdx.y * 16 + rloc;
    float4 A0 = g_iA[b][rbase+0], A1 = g_iA[b][rbase+1];
    float4 A2 = g_iA[b][rbase+2], A3 = g_iA[b][rbase+3];
    const float4* PU = &g_u4[b][half * 2048];

    float m0 = 3.4e38f, m1 = 3.4e38f, m2 = 3.4e38f, m3 = 3.4e38f;
    #pragma unroll 2
    for (int k = lane; k < 2048; k += 32) {
        float4 U = __ldg(PU + k);
        float d0 = fmaf(A0.x, U.x, fmaf(A0.y, U.y, A0.z * U.z)); m0 = fminf(m0, d0*d0);
        float d1 = fmaf(A1.x, U.x, fmaf(A1.y, U.y, A1.z * U.z)); m1 = fminf(m1, d1*d1);
        float d2 = fmaf(A2.x, U.x, fmaf(A2.y, U.y, A2.z * U.z)); m2 = fminf(m2, d2*d2);
        float d3 = fmaf(A3.x, U.x, fmaf(A3.y, U.y, A3.z * U.z)); m3 = fminf(m3, d3*d3);
    }
    m0 = wminf(m0); m1 = wminf(m1); m2 = wminf(m2); m3 = wminf(m3);
    if (lane == 0) {
        sMin[half][rloc+0] = m0; sMin[half][rloc+1] = m1;
        sMin[half][rloc+2] = m2; sMin[half][rloc+3] = m3;
    }
    __syncthreads();
    float cM0 = sqapx(fmaxf(A0.w - fminf(sMin[0][rloc+0], sMin[1][rloc+0]), 0.f)) * C50F;
    float cM1 = sqapx(fmaxf(A1.w - fminf(sMin[0][rloc+1], sMin[1][rloc+1]), 0.f)) * C50F;
    float cM2 = sqapx(fmaxf(A2.w - fminf(sMin[0][rloc+2], sMin[1][rloc+2]), 0.f)) * C50F;
    float cM3 = sqapx(fmaxf(A3.w - fminf(sMin[0][rloc+3], sMin[1][rloc+3]), 0.f)) * C50F;

    float s0 = 0.f, s1 = 0.f, s2 = 0.f, s3 = 0.f;
    for (int k = lane; k < 2048; k += 32) {
        float4 U = __ldg(PU + k);
        float d0 = fmaf(A0.x, U.x, fmaf(A0.y, U.y, A0.z * U.z));
        s0 += ex2f(fmaf(sqapx(fmaxf(fmaf(-d0, d0, A0.w), 0.f)), C50F, -cM0));
        float d1 = fmaf(A1.x, U.x, fmaf(A1.y, U.y, A1.z * U.z));
        s1 += ex2f(fmaf(sqapx(fmaxf(fmaf(-d1, d1, A1.w), 0.f)), C50F, -cM1));
        float d2 = fmaf(A2.x, U.x, fmaf(A2.y, U.y, A2.z * U.z));
        s2 += ex2f(fmaf(sqapx(fmaxf(fmaf(-d2, d2, A2.w), 0.f)), C50F, -cM2));
        float d3 = fmaf(A3.x, U.x, fmaf(A3.y, U.y, A3.z * U.z));
        s3 += ex2f(fmaf(sqapx(fmaxf(fmaf(-d3, d3, A3.w), 0.f)), C50F, -cM3));
    }
    s0 = wsumf(s0); s1 = wsumf(s1); s2 = wsumf(s2); s3 = wsumf(s3);
    if (lane == 0) {
        sSum[half][rloc+0] = s0; sSum[half][rloc+1] = s1;
        sSum[half][rloc+2] = s2; sSum[half][rloc+3] = s3;
    }
    __syncthreads();
    if (threadIdx.x < 16) {
        int r = threadIdx.x;
        int row = blockIdx.y * 16 + r;
        float m = fminf(sMin[0][r], sMin[1][r]);
        float cM = sqapx(fmaxf(g_iA[b][row].w - m, 0.f)) * C50F;
        float S = sSum[0][r] + sSum[1][r];
        g_cL[b][row] = cM + log2f(S);
    }
}

// ---------------------------------------------------------------------------
// col: 16 cols/block. Warp = 4 cols (w&3) x i-half (w>>2). a2 = A.T + T.w.
// Loads per i: A (float4) + cL (scalar). -> LSEcol2.
// ---------------------------------------------------------------------------
__global__ void __launch_bounds__(256, 4) k_col() {
    __shared__ float sSum[2][16];
    int b = blockIdx.x;
    int lane = threadIdx.x & 31, w = threadIdx.x >> 5;
    int half = w >> 2;
    int cloc = (w & 3) * 4;
    int cbase = blockIdx.y * 16 + cloc;
    float4 U0 = g_jU[b][cbase+0], U1 = g_jU[b][cbase+1];
    float4 U2 = g_jU[b][cbase+2], U3 = g_jU[b][cbase+3];
    float4 T0 = g_jT[b][cbase+0], T1 = g_jT[b][cbase+1];
    float4 T2 = g_jT[b][cbase+2], T3 = g_jT[b][cbase+3];
    const float4* PA = &g_iA[b][half * 2048];
    const float* PL  = &g_cL[b][half * 2048];

    float c0 = 0.f, c1 = 0.f, c2 = 0.f, c3 = 0.f;
    for (int k = lane; k < 2048; k += 32) {
        float4 A = __ldg(PA + k);
        float nL = -__ldg(PL + k);
        float d0 = fmaf(A.x, U0.x, fmaf(A.y, U0.y, A.z * U0.z));
        float e0 = ex2f(fmaf(sqapx(fmaxf(fmaf(-d0, d0, A.w), 0.f)), C50F, nL));
        float a0 = fmaf(A.x, T0.x, fmaf(A.y, T0.y, fmaf(A.z, T0.z, T0.w)));
        c0 += ex2f(fmaf(-a0, e0, a0));
        float d1 = fmaf(A.x, U1.x, fmaf(A.y, U1.y, A.z * U1.z));
        float e1 = ex2f(fmaf(sqapx(fmaxf(fmaf(-d1, d1, A.w), 0.f)), C50F, nL));
        float a1 = fmaf(A.x, T1.x, fmaf(A.y, T1.y, fmaf(A.z, T1.z, T1.w)));
        c1 += ex2f(fmaf(-a1, e1, a1));
        float d2 = fmaf(A.x, U2.x, fmaf(A.y, U2.y, A.z * U2.z));
        float e2 = ex2f(fmaf(sqapx(fmaxf(fmaf(-d2, d2, A.w), 0.f)), C50F, nL));
        float a2 = fmaf(A.x, T2.x, fmaf(A.y, T2.y, fmaf(A.z, T2.z, T2.w)));
        c2 += ex2f(fmaf(-a2, e2, a2));
        float d3 = fmaf(A.x, U3.x, fmaf(A.y, U3.y, A.z * U3.z));
        float e3 = ex2f(fmaf(sqapx(fmaxf(fmaf(-d3, d3, A.w), 0.f)), C50F, nL));
        float a3 = fmaf(A.x, T3.x, fmaf(A.y, T3.y, fmaf(A.z, T3.z, T3.w)));
        c3 += ex2f(fmaf(-a3, e3, a3));
    }
    c0 = wsumf(c0); c1 = wsumf(c1); c2 = wsumf(c2); c3 = wsumf(c3);
    if (lane == 0) {
        sSum[half][cloc+0] = c0; sSum[half][cloc+1] = c1;
        sSum[half][cloc+2] = c2; sSum[half][cloc+3] = c3;
    }
    __syncthreads();
    if (threadIdx.x < 16) {
        int c = threadIdx.x;
        int col = blockIdx.y * 16 + c;
        float S = sSum[0][c] + sSum[1][c];
        ((float*)&g_jU[b][col])[3] = log2f(S);        // LSEcol2
    }
}

// ---------------------------------------------------------------------------
// out: R2 shape — 8 rows/block, warp = 4 rows (w&1) x j-quarter (w>>1).
// grid (BT, NPIX/8) = 1024 blocks. a2 = A.T + T.w; cL scalar.
// ---------------------------------------------------------------------------
__global__ void __launch_bounds__(256, 4) k_out(float* __restrict__ out) {
    __shared__ float sO[4][8][3];
    int b = blockIdx.x;
    int lane = threadIdx.x & 31, w = threadIdx.x >> 5;
    int rg = w & 1;
    int sp = w >> 1;
    int rbase = blockIdx.y * 8 + rg * 4;
    float4 A0 = g_iA[b][rbase+0], A1 = g_iA[b][rbase+1];
    float4 A2 = g_iA[b][rbase+2], A3 = g_iA[b][rbase+3];
    float nL0 = -g_cL[b][rbase+0], nL1 = -g_cL[b][rbase+1];
    float nL2 = -g_cL[b][rbase+2], nL3 = -g_cL[b][rbase+3];
    const float4* PU = &g_jU[b][sp * 1024];
    const float4* PT = &g_jT[b][sp * 1024];
    const float4* PS = &g_jS[b][sp * 1024];

    float x0=0,y0=0,z0=0, x1=0,y1=0,z1=0, x2=0,y2=0,z2=0, x3=0,y3=0,z3=0;
    for (int k = lane; k < 1024; k += 32) {
        float4 U = __ldg(PU + k);
        float4 T = __ldg(PT + k);
        float4 S = __ldg(PS + k);
        float d0 = fmaf(A0.x, U.x, fmaf(A0.y, U.y, A0.z * U.z));
        float e0 = ex2f(fmaf(sqapx(fmaxf(fmaf(-d0, d0, A0.w), 0.f)), C50F, nL0));
        float a0 = fmaf(A0.x, T.x, fmaf(A0.y, T.y, fmaf(A0.z, T.z, T.w)));
        float p0 = ex2f(fmaf(-a0, e0, a0 - U.w));
        x0 = fmaf(p0, S.x, x0); y0 = fmaf(p0, S.y, y0); z0 = fmaf(p0, S.z, z0);
        float d1 = fmaf(A1.x, U.x, fmaf(A1.y, U.y, A1.z * U.z));
        float e1 = ex2f(fmaf(sqapx(fmaxf(fmaf(-d1, d1, A1.w), 0.f)), C50F, nL1));
        float a1 = fmaf(A1.x, T.x, fmaf(A1.y, T.y, fmaf(A1.z, T.z, T.w)));
        float p1 = ex2f(fmaf(-a1, e1, a1 - U.w));
        x1 = fmaf(p1, S.x, x1); y1 = fmaf(p1, S.y, y1); z1 = fmaf(p1, S.z, z1);
        float d2 = fmaf(A2.x, U.x, fmaf(A2.y, U.y, A2.z * U.z));
        float e2 = ex2f(fmaf(sqapx(fmaxf(fmaf(-d2, d2, A2.w), 0.f)), C50F, nL2));
        float a2 = fmaf(A2.x, T.x, fmaf(A2.y, T.y, fmaf(A2.z, T.z, T.w)));
        float p2 = ex2f(fmaf(-a2, e2, a2 - U.w));
        x2 = fmaf(p2, S.x, x2); y2 = fmaf(p2, S.y, y2); z2 = fmaf(p2, S.z, z2);
        float d3 = fmaf(A3.x, U.x, fmaf(A3.y, U.y, A3.z * U.z));
        float e3 = ex2f(fmaf(sqapx(fmaxf(fmaf(-d3, d3, A3.w), 0.f)), C50F, nL3));
        float a3 = fmaf(A3.x, T.x, fmaf(A3.y, T.y, fmaf(A3.z, T.z, T.w)));
        float p3 = ex2f(fmaf(-a3, e3, a3 - U.w));
        x3 = fmaf(p3, S.x, x3); y3 = fmaf(p3, S.y, y3); z3 = fmaf(p3, S.z, z3);
    }
    x0 = wsumf(x0); y0 = wsumf(y0); z0 = wsumf(z0);
    x1 = wsumf(x1); y1 = wsumf(y1); z1 = wsumf(z1);
    x2 = wsumf(x2); y2 = wsumf(y2); z2 = wsumf(z2);
    x3 = wsumf(x3); y3 = wsumf(y3); z3 = wsumf(z3);
    if (lane == 0) {
        int r = rg * 4;
        sO[sp][r+0][0] = x0; sO[sp][r+0][1] = y0; sO[sp][r+0][2] = z0;
        sO[sp][r+1][0] = x1; sO[sp][r+1][1] = y1; sO[sp][r+1][2] = z1;
        sO[sp][r+2][0] = x2; sO[sp][r+2][1] = y2; sO[sp][r+2][2] = z2;
        sO[sp][r+3][0] = x3; sO[sp][r+3][1] = y3; sO[sp][r+3][2] = z3;
    }
    __syncthreads();
    if (threadIdx.x < 24) {
        int r = threadIdx.x / 3, ch = threadIdx.x % 3;
        float v = sO[0][r][ch] + sO[1][r][ch] + sO[2][r][ch] + sO[3][r][ch];
        out[b * NPIX * 3 + (blockIdx.y * 8 + r) * 3 + ch] = v;
    }
}

// ---------------------------------------------------------------------------
extern "C" void kernel_launch(void* const* d_in, const int* in_sizes, int n_in,
                              void* d_out, int out_size) {
    const float* f_tar = (const float*)d_in[0];
    const float* f_src = (const float*)d_in[1];
    const float* Km    = (const float*)d_in[2];
    const float* Rm    = (const float*)d_in[3];
    const float* tv    = (const float*)d_in[4];
    float* out = (float*)d_out;

    k_pre     <<<dim3(BT, 16), 256>>>(f_tar, f_src, Km, Rm, tv);
    k_rowstats<<<dim3(BT, NPIX/16), 256>>>();
    k_col     <<<dim3(BT, NPIX/16), 256>>>();
    k_out     <<<dim3(BT, NPIX/8),  256>>>(out);
}

// round 9
// speedup vs baseline: 1.1530x; 1.0481x over previous
#include <cuda_runtime.h>

#define NPIX 4096
#define BT 2

// 50*log2(e), log2(e)
#define C50F   72.13475204444817f
#define CL2E   1.4426950408889634f

// ---------------------------------------------------------------------------
// Scratch (device globals)
// ---------------------------------------------------------------------------
__device__ float4 g_u4 [BT][NPIX];            // (u0,u1,u2,-)
__device__ float4 g_iA [BT][NPIX];            // (a0,a1,a2,|a|^2)   a = fs - o
__device__ float4 g_iF [BT][NPIX];            // (fs0,fs1,fs2, cLrow)
__device__ float  g_cL [BT][NPIX];            // cLrow = cM + log2 Srow (for k_out)
__device__ float4 g_jU [BT][NPIX];            // (u0,u1,u2, LSEcol2)
__device__ float4 g_jT [BT][NPIX];            // (ft*log2e x3, o.(ft*log2e))
__device__ float4 g_jS [BT][NPIX];            // (fs x3, -)

// ---------------------------------------------------------------------------
__device__ __forceinline__ float ex2f(float x) {
    float y; asm("ex2.approx.ftz.f32 %0, %1;" : "=f"(y) : "f"(x)); return y;
}
__device__ __forceinline__ float sqapx(float x) {
    float y; asm("sqrt.approx.ftz.f32 %0, %1;" : "=f"(y) : "f"(x)); return y;
}
__device__ __forceinline__ float wsumf(float v) {
    #pragma unroll
    for (int o = 16; o; o >>= 1) v += __shfl_xor_sync(0xffffffffu, v, o);
    return v;
}
__device__ __forceinline__ float wminf(float v) {
    #pragma unroll
    for (int o = 16; o; o >>= 1) v = fminf(v, __shfl_xor_sync(0xffffffffu, v, o));
    return v;
}

// ---------------------------------------------------------------------------
// Precompute per-i / per-j records (double precision geometry), parallel.
// ---------------------------------------------------------------------------
__global__ void k_pre(const float* __restrict__ f_tar, const float* __restrict__ f_src,
                      const float* __restrict__ Km, const float* __restrict__ Rm,
                      const float* __restrict__ tv) {
    int b = blockIdx.x;
    double Kd[9], Rd[9], td[3];
    #pragma unroll
    for (int m = 0; m < 9; m++) { Kd[m] = (double)Km[b*9+m]; Rd[m] = (double)Rm[b*9+m]; }
    #pragma unroll
    for (int m = 0; m < 3; m++) td[m] = (double)tv[b*3+m];

    double c00 = Kd[4]*Kd[8] - Kd[5]*Kd[7];
    double c10 = Kd[5]*Kd[6] - Kd[3]*Kd[8];
    double c20 = Kd[3]*Kd[7] - Kd[4]*Kd[6];
    double det = Kd[0]*c00 + Kd[1]*c10 + Kd[2]*c20;
    double id  = 1.0 / det;
    double Ki[9];
    Ki[0] = c00*id; Ki[1] = (Kd[2]*Kd[7]-Kd[1]*Kd[8])*id; Ki[2] = (Kd[1]*Kd[5]-Kd[2]*Kd[4])*id;
    Ki[3] = c10*id; Ki[4] = (Kd[0]*Kd[8]-Kd[2]*Kd[6])*id; Ki[5] = (Kd[2]*Kd[3]-Kd[0]*Kd[5])*id;
    Ki[6] = c20*id; Ki[7] = (Kd[1]*Kd[6]-Kd[0]*Kd[7])*id; Ki[8] = (Kd[0]*Kd[4]-Kd[1]*Kd[3])*id;

    double o0 = Kd[0]*td[0] + Kd[1]*td[1] + Kd[2]*td[2];
    double o1 = Kd[3]*td[0] + Kd[4]*td[1] + Kd[5]*td[2];
    double o2 = Kd[6]*td[0] + Kd[7]*td[1] + Kd[8]*td[2];
    float of0 = (float)o0, of1 = (float)o1, of2 = (float)o2;

    const float* fs = f_src + b*3*NPIX;
    const float* ft = f_tar + b*3*NPIX;

    int j = blockIdx.y * 256 + threadIdx.x;
    {
        double px = (double)(j >> 6), py = (double)(j & 63);
        double ca = Ki[0]*px + Ki[1]*py + Ki[2];
        double cb = Ki[3]*px + Ki[4]*py + Ki[5];
        double cc = Ki[6]*px + Ki[7]*py + Ki[8];
        double ra = Rd[0]*ca + Rd[1]*cb + Rd[2]*cc + td[0];
        double rb = Rd[3]*ca + Rd[4]*cb + Rd[5]*cc + td[1];
        double rc = Rd[6]*ca + Rd[7]*cb + Rd[8]*cc + td[2];
        double da = Kd[0]*ra + Kd[1]*rb + Kd[2]*rc - o0;
        double db = Kd[3]*ra + Kd[4]*rb + Kd[5]*rc - o1;
        double dc = Kd[6]*ra + Kd[7]*rb + Kd[8]*rc - o2;
        double inv = 1.0 / sqrt(da*da + db*db + dc*dc);
        float u0 = (float)(da*inv), u1 = (float)(db*inv), u2 = (float)(dc*inv);

        float t0 = ft[j]*CL2E, t1 = ft[NPIX + j]*CL2E, t2 = ft[2*NPIX + j]*CL2E;
        float s0 = fs[j], s1 = fs[NPIX + j], s2 = fs[2*NPIX + j];
        float oT = of0*t0 + of1*t1 + of2*t2;          // o . (ft*log2e)
        g_u4[b][j] = make_float4(u0, u1, u2, 0.f);
        g_jU[b][j] = make_float4(u0, u1, u2, 0.f);
        g_jT[b][j] = make_float4(t0, t1, t2, oT);
        g_jS[b][j] = make_float4(s0, s1, s2, 0.f);

        float a0 = s0 - of0, a1 = s1 - of1, a2 = s2 - of2;
        float na2 = (float)((double)a0*a0 + (double)a1*a1 + (double)a2*a2);
        g_iA[b][j] = make_float4(a0, a1, a2, na2);
        g_iF[b][j] = make_float4(s0, s1, s2, 0.f);
    }
}

// ---------------------------------------------------------------------------
// rowstats: 16 rows/block. Warp = 4 rows (w&3) x j-half (w>>2, 2048 each).
// Writes cLrow = cM + log2(Srow) into BOTH g_iF.w (for k_col) and g_cL (k_out).
// ---------------------------------------------------------------------------
__global__ void __launch_bounds__(256, 4) k_rowstats() {
    __shared__ float sMin[2][16], sSum[2][16];
    int b = blockIdx.x;
    int lane = threadIdx.x & 31, w = threadIdx.x >> 5;
    int half = w >> 2;
    int rloc = (w & 3) * 4;
    int rbase = blockIdx.y * 16 + rloc;
    float4 A0 = g_iA[b][rbase+0], A1 = g_iA[b][rbase+1];
    float4 A2 = g_iA[b][rbase+2], A3 = g_iA[b][rbase+3];
    const float4* PU = &g_u4[b][half * 2048];

    float m0 = 3.4e38f, m1 = 3.4e38f, m2 = 3.4e38f, m3 = 3.4e38f;
    #pragma unroll 2
    for (int k = lane; k < 2048; k += 32) {
        float4 U = __ldg(PU + k);
        float d0 = fmaf(A0.x, U.x, fmaf(A0.y, U.y, A0.z * U.z)); m0 = fminf(m0, d0*d0);
        float d1 = fmaf(A1.x, U.x, fmaf(A1.y, U.y, A1.z * U.z)); m1 = fminf(m1, d1*d1);
        float d2 = fmaf(A2.x, U.x, fmaf(A2.y, U.y, A2.z * U.z)); m2 = fminf(m2, d2*d2);
        float d3 = fmaf(A3.x, U.x, fmaf(A3.y, U.y, A3.z * U.z)); m3 = fminf(m3, d3*d3);
    }
    m0 = wminf(m0); m1 = wminf(m1); m2 = wminf(m2); m3 = wminf(m3);
    if (lane == 0) {
        sMin[half][rloc+0] = m0; sMin[half][rloc+1] = m1;
        sMin[half][rloc+2] = m2; sMin[half][rloc+3] = m3;
    }
    __syncthreads();
    float cM0 = sqapx(fmaxf(A0.w - fminf(sMin[0][rloc+0], sMin[1][rloc+0]), 0.f)) * C50F;
    float cM1 = sqapx(fmaxf(A1.w - fminf(sMin[0][rloc+1], sMin[1][rloc+1]), 0.f)) * C50F;
    float cM2 = sqapx(fmaxf(A2.w - fminf(sMin[0][rloc+2], sMin[1][rloc+2]), 0.f)) * C50F;
    float cM3 = sqapx(fmaxf(A3.w - fminf(sMin[0][rloc+3], sMin[1][rloc+3]), 0.f)) * C50F;

    float s0 = 0.f, s1 = 0.f, s2 = 0.f, s3 = 0.f;
    for (int k = lane; k < 2048; k += 32) {
        float4 U = __ldg(PU + k);
        float d0 = fmaf(A0.x, U.x, fmaf(A0.y, U.y, A0.z * U.z));
        s0 += ex2f(fmaf(sqapx(fmaxf(fmaf(-d0, d0, A0.w), 0.f)), C50F, -cM0));
        float d1 = fmaf(A1.x, U.x, fmaf(A1.y, U.y, A1.z * U.z));
        s1 += ex2f(fmaf(sqapx(fmaxf(fmaf(-d1, d1, A1.w), 0.f)), C50F, -cM1));
        float d2 = fmaf(A2.x, U.x, fmaf(A2.y, U.y, A2.z * U.z));
        s2 += ex2f(fmaf(sqapx(fmaxf(fmaf(-d2, d2, A2.w), 0.f)), C50F, -cM2));
        float d3 = fmaf(A3.x, U.x, fmaf(A3.y, U.y, A3.z * U.z));
        s3 += ex2f(fmaf(sqapx(fmaxf(fmaf(-d3, d3, A3.w), 0.f)), C50F, -cM3));
    }
    s0 = wsumf(s0); s1 = wsumf(s1); s2 = wsumf(s2); s3 = wsumf(s3);
    if (lane == 0) {
        sSum[half][rloc+0] = s0; sSum[half][rloc+1] = s1;
        sSum[half][rloc+2] = s2; sSum[half][rloc+3] = s3;
    }
    __syncthreads();
    if (threadIdx.x < 16) {
        int r = threadIdx.x;
        int row = blockIdx.y * 16 + r;
        float m = fminf(sMin[0][r], sMin[1][r]);
        float cM = sqapx(fmaxf(g_iA[b][row].w - m, 0.f)) * C50F;
        float cL = cM + log2f(sSum[0][r] + sSum[1][r]);
        ((float*)&g_iF[b][row])[3] = cL;
        g_cL[b][row] = cL;
    }
}

// ---------------------------------------------------------------------------
// col: 16 cols/block (R6 form). Warp = 4 cols (w&3) x i-half (w>>2).
// Loads A (float4) + F (float4, fs+cL); a2 = F.T. -> LSEcol2.
// ---------------------------------------------------------------------------
__global__ void __launch_bounds__(256, 4) k_col() {
    __shared__ float sSum[2][16];
    int b = blockIdx.x;
    int lane = threadIdx.x & 31, w = threadIdx.x >> 5;
    int half = w >> 2;
    int cloc = (w & 3) * 4;
    int cbase = blockIdx.y * 16 + cloc;
    float4 U0 = g_jU[b][cbase+0], U1 = g_jU[b][cbase+1];
    float4 U2 = g_jU[b][cbase+2], U3 = g_jU[b][cbase+3];
    float4 T0 = g_jT[b][cbase+0], T1 = g_jT[b][cbase+1];
    float4 T2 = g_jT[b][cbase+2], T3 = g_jT[b][cbase+3];
    const float4* PA = &g_iA[b][half * 2048];
    const float4* PF = &g_iF[b][half * 2048];

    float c0 = 0.f, c1 = 0.f, c2 = 0.f, c3 = 0.f;
    for (int k = lane; k < 2048; k += 32) {
        float4 A = __ldg(PA + k);
        float4 F = __ldg(PF + k);
        float nL = -F.w;
        float d0 = fmaf(A.x, U0.x, fmaf(A.y, U0.y, A.z * U0.z));
        float e0 = ex2f(fmaf(sqapx(fmaxf(fmaf(-d0, d0, A.w), 0.f)), C50F, nL));
        float a0 = fmaf(F.x, T0.x, fmaf(F.y, T0.y, F.z * T0.z));
        c0 += ex2f(fmaf(-a0, e0, a0));
        float d1 = fmaf(A.x, U1.x, fmaf(A.y, U1.y, A.z * U1.z));
        float e1 = ex2f(fmaf(sqapx(fmaxf(fmaf(-d1, d1, A.w), 0.f)), C50F, nL));
        float a1 = fmaf(F.x, T1.x, fmaf(F.y, T1.y, F.z * T1.z));
        c1 += ex2f(fmaf(-a1, e1, a1));
        float d2 = fmaf(A.x, U2.x, fmaf(A.y, U2.y, A.z * U2.z));
        float e2 = ex2f(fmaf(sqapx(fmaxf(fmaf(-d2, d2, A.w), 0.f)), C50F, nL));
        float a2 = fmaf(F.x, T2.x, fmaf(F.y, T2.y, F.z * T2.z));
        c2 += ex2f(fmaf(-a2, e2, a2));
        float d3 = fmaf(A.x, U3.x, fmaf(A.y, U3.y, A.z * U3.z));
        float e3 = ex2f(fmaf(sqapx(fmaxf(fmaf(-d3, d3, A.w), 0.f)), C50F, nL));
        float a3 = fmaf(F.x, T3.x, fmaf(F.y, T3.y, F.z * T3.z));
        c3 += ex2f(fmaf(-a3, e3, a3));
    }
    c0 = wsumf(c0); c1 = wsumf(c1); c2 = wsumf(c2); c3 = wsumf(c3);
    if (lane == 0) {
        sSum[half][cloc+0] = c0; sSum[half][cloc+1] = c1;
        sSum[half][cloc+2] = c2; sSum[half][cloc+3] = c3;
    }
    __syncthreads();
    if (threadIdx.x < 16) {
        int c = threadIdx.x;
        int col = blockIdx.y * 16 + c;
        float S = sSum[0][c] + sSum[1][c];
        ((float*)&g_jU[b][col])[3] = log2f(S);        // LSEcol2
    }
}

// ---------------------------------------------------------------------------
// out: 8 rows/block, warp = 4 rows (w&1) x j-quarter (w>>1).
// grid (BT, NPIX/8) = 1024 blocks. a2 = A.T + T.w; cL scalar.
// ---------------------------------------------------------------------------
__global__ void __launch_bounds__(256, 4) k_out(float* __restrict__ out) {
    __shared__ float sO[4][8][3];
    int b = blockIdx.x;
    int lane = threadIdx.x & 31, w = threadIdx.x >> 5;
    int rg = w & 1;
    int sp = w >> 1;
    int rbase = blockIdx.y * 8 + rg * 4;
    float4 A0 = g_iA[b][rbase+0], A1 = g_iA[b][rbase+1];
    float4 A2 = g_iA[b][rbase+2], A3 = g_iA[b][rbase+3];
    float nL0 = -g_cL[b][rbase+0], nL1 = -g_cL[b][rbase+1];
    float nL2 = -g_cL[b][rbase+2], nL3 = -g_cL[b][rbase+3];
    const float4* PU = &g_jU[b][sp * 1024];
    const float4* PT = &g_jT[b][sp * 1024];
    const float4* PS = &g_jS[b][sp * 1024];

    float x0=0,y0=0,z0=0, x1=0,y1=0,z1=0, x2=0,y2=0,z2=0, x3=0,y3=0,z3=0;
    for (int k = lane; k < 1024; k += 32) {
        float4 U = __ldg(PU + k);
        float4 T = __ldg(PT + k);
        float4 S = __ldg(PS + k);
        float d0 = fmaf(A0.x, U.x, fmaf(A0.y, U.y, A0.z * U.z));
        float e0 = ex2f(fmaf(sqapx(fmaxf(fmaf(-d0, d0, A0.w), 0.f)), C50F, nL0));
        float a0 = fmaf(A0.x, T.x, fmaf(A0.y, T.y, fmaf(A0.z, T.z, T.w)));
        float p0 = ex2f(fmaf(-a0, e0, a0 - U.w));
        x0 = fmaf(p0, S.x, x0); y0 = fmaf(p0, S.y, y0); z0 = fmaf(p0, S.z, z0);
        float d1 = fmaf(A1.x, U.x, fmaf(A1.y, U.y, A1.z * U.z));
        float e1 = ex2f(fmaf(sqapx(fmaxf(fmaf(-d1, d1, A1.w), 0.f)), C50F, nL1));
        float a1 = fmaf(A1.x, T.x, fmaf(A1.y, T.y, fmaf(A1.z, T.z, T.w)));
        float p1 = ex2f(fmaf(-a1, e1, a1 - U.w));
        x1 = fmaf(p1, S.x, x1); y1 = fmaf(p1, S.y, y1); z1 = fmaf(p1, S.z, z1);
        float d2 = fmaf(A2.x, U.x, fmaf(A2.y, U.y, A2.z * U.z));
        float e2 = ex2f(fmaf(sqapx(fmaxf(fmaf(-d2, d2, A2.w), 0.f)), C50F, nL2));
        float a2 = fmaf(A2.x, T.x, fmaf(A2.y, T.y, fmaf(A2.z, T.z, T.w)));
        float p2 = ex2f(fmaf(-a2, e2, a2 - U.w));
        x2 = fmaf(p2, S.x, x2); y2 = fmaf(p2, S.y, y2); z2 = fmaf(p2, S.z, z2);
        float d3 = fmaf(A3.x, U.x, fmaf(A3.y, U.y, A3.z * U.z));
        float e3 = ex2f(fmaf(sqapx(fmaxf(fmaf(-d3, d3, A3.w), 0.f)), C50F, nL3));
        float a3 = fmaf(A3.x, T.x, fmaf(A3.y, T.y, fmaf(A3.z, T.z, T.w)));
        float p3 = ex2f(fmaf(-a3, e3, a3 - U.w));
        x3 = fmaf(p3, S.x, x3); y3 = fmaf(p3, S.y, y3); z3 = fmaf(p3, S.z, z3);
    }
    x0 = wsumf(x0); y0 = wsumf(y0); z0 = wsumf(z0);
    x1 = wsumf(x1); y1 = wsumf(y1); z1 = wsumf(z1);
    x2 = wsumf(x2); y2 = wsumf(y2); z2 = wsumf(z2);
    x3 = wsumf(x3); y3 = wsumf(y3); z3 = wsumf(z3);
    if (lane == 0) {
        int r = rg * 4;
        sO[sp][r+0][0] = x0; sO[sp][r+0][1] = y0; sO[sp][r+0][2] = z0;
        sO[sp][r+1][0] = x1; sO[sp][r+1][1] = y1; sO[sp][r+1][2] = z1;
        sO[sp][r+2][0] = x2; sO[sp][r+2][1] = y2; sO[sp][r+2][2] = z2;
        sO[sp][r+3][0] = x3; sO[sp][r+3][1] = y3; sO[sp][r+3][2] = z3;
    }
    __syncthreads();
    if (threadIdx.x < 24) {
        int r = threadIdx.x / 3, ch = threadIdx.x % 3;
        float v = sO[0][r][ch] + sO[1][r][ch] + sO[2][r][ch] + sO[3][r][ch];
        out[b * NPIX * 3 + (blockIdx.y * 8 + r) * 3 + ch] = v;
    }
}

// ---------------------------------------------------------------------------
extern "C" void kernel_launch(void* const* d_in, const int* in_sizes, int n_in,
                              void* d_out, int out_size) {
    const float* f_tar = (const float*)d_in[0];
    const float* f_src = (const float*)d_in[1];
    const float* Km    = (const float*)d_in[2];
    const float* Rm    = (const float*)d_in[3];
    const float* tv    = (const float*)d_in[4];
    float* out = (float*)d_out;

    k_pre     <<<dim3(BT, 16), 256>>>(f_tar, f_src, Km, Rm, tv);
    k_rowstats<<<dim3(BT, NPIX/16), 256>>>();
    k_col     <<<dim3(BT, NPIX/16), 256>>>();
    k_out     <<<dim3(BT, NPIX/8),  256>>>(out);
}

// round 10
// speedup vs baseline: 1.3525x; 1.1730x over previous
#include <cuda_runtime.h>

#define NPIX 4096
#define BT 2

// 50*log2(e), log2(e)
#define C50F   72.13475204444817f
#define CL2E   1.4426950408889634f

// ---------------------------------------------------------------------------
// Scratch (device globals)
// ---------------------------------------------------------------------------
__device__ float4 g_u4 [BT][NPIX];            // (u0,u1,u2,-)
__device__ float4 g_iA [BT][NPIX];            // (a0,a1,a2,|a|^2)   a = fs - o
__device__ float4 g_iF [BT][NPIX];            // (fs0,fs1,fs2, cLrow)
__device__ float  g_cL [BT][NPIX];            // cLrow = cM + log2 Srow (for k_out)
__device__ float4 g_jU [BT][NPIX];            // (u0,u1,u2, LSEcol2)
__device__ float4 g_jT [BT][NPIX];            // (ft*log2e x3, o.(ft*log2e))
__device__ float4 g_jS [BT][NPIX];            // (fs x3, -)

// ---------------------------------------------------------------------------
__device__ __forceinline__ float ex2f(float x) {
    float y; asm("ex2.approx.ftz.f32 %0, %1;" : "=f"(y) : "f"(x)); return y;
}
__device__ __forceinline__ float sqapx(float x) {
    float y; asm("sqrt.approx.ftz.f32 %0, %1;" : "=f"(y) : "f"(x)); return y;
}
__device__ __forceinline__ float wsumf(float v) {
    #pragma unroll
    for (int o = 16; o; o >>= 1) v += __shfl_xor_sync(0xffffffffu, v, o);
    return v;
}
__device__ __forceinline__ float wminf(float v) {
    #pragma unroll
    for (int o = 16; o; o >>= 1) v = fminf(v, __shfl_xor_sync(0xffffffffu, v, o));
    return v;
}

// ---------------------------------------------------------------------------
// Precompute per-i / per-j records (double precision geometry), parallel.
// ---------------------------------------------------------------------------
__global__ void k_pre(const float* __restrict__ f_tar, const float* __restrict__ f_src,
                      const float* __restrict__ Km, const float* __restrict__ Rm,
                      const float* __restrict__ tv) {
    int b = blockIdx.x;
    double Kd[9], Rd[9], td[3];
    #pragma unroll
    for (int m = 0; m < 9; m++) { Kd[m] = (double)Km[b*9+m]; Rd[m] = (double)Rm[b*9+m]; }
    #pragma unroll
    for (int m = 0; m < 3; m++) td[m] = (double)tv[b*3+m];

    double c00 = Kd[4]*Kd[8] - Kd[5]*Kd[7];
    double c10 = Kd[5]*Kd[6] - Kd[3]*Kd[8];
    double c20 = Kd[3]*Kd[7] - Kd[4]*Kd[6];
    double det = Kd[0]*c00 + Kd[1]*c10 + Kd[2]*c20;
    double id  = 1.0 / det;
    double Ki[9];
    Ki[0] = c00*id; Ki[1] = (Kd[2]*Kd[7]-Kd[1]*Kd[8])*id; Ki[2] = (Kd[1]*Kd[5]-Kd[2]*Kd[4])*id;
    Ki[3] = c10*id; Ki[4] = (Kd[0]*Kd[8]-Kd[2]*Kd[6])*id; Ki[5] = (Kd[2]*Kd[3]-Kd[0]*Kd[5])*id;
    Ki[6] = c20*id; Ki[7] = (Kd[1]*Kd[6]-Kd[0]*Kd[7])*id; Ki[8] = (Kd[0]*Kd[4]-Kd[1]*Kd[3])*id;

    double o0 = Kd[0]*td[0] + Kd[1]*td[1] + Kd[2]*td[2];
    double o1 = Kd[3]*td[0] + Kd[4]*td[1] + Kd[5]*td[2];
    double o2 = Kd[6]*td[0] + Kd[7]*td[1] + Kd[8]*td[2];
    float of0 = (float)o0, of1 = (float)o1, of2 = (float)o2;

    const float* fs = f_src + b*3*NPIX;
    const float* ft = f_tar + b*3*NPIX;

    int j = blockIdx.y * 256 + threadIdx.x;
    {
        double px = (double)(j >> 6), py = (double)(j & 63);
        double ca = Ki[0]*px + Ki[1]*py + Ki[2];
        double cb = Ki[3]*px + Ki[4]*py + Ki[5];
        double cc = Ki[6]*px + Ki[7]*py + Ki[8];
        double ra = Rd[0]*ca + Rd[1]*cb + Rd[2]*cc + td[0];
        double rb = Rd[3]*ca + Rd[4]*cb + Rd[5]*cc + td[1];
        double rc = Rd[6]*ca + Rd[7]*cb + Rd[8]*cc + td[2];
        double da = Kd[0]*ra + Kd[1]*rb + Kd[2]*rc - o0;
        double db = Kd[3]*ra + Kd[4]*rb + Kd[5]*rc - o1;
        double dc = Kd[6]*ra + Kd[7]*rb + Kd[8]*rc - o2;
        double inv = 1.0 / sqrt(da*da + db*db + dc*dc);
        float u0 = (float)(da*inv), u1 = (float)(db*inv), u2 = (float)(dc*inv);

        float t0 = ft[j]*CL2E, t1 = ft[NPIX + j]*CL2E, t2 = ft[2*NPIX + j]*CL2E;
        float s0 = fs[j], s1 = fs[NPIX + j], s2 = fs[2*NPIX + j];
        float oT = of0*t0 + of1*t1 + of2*t2;          // o . (ft*log2e)
        g_u4[b][j] = make_float4(u0, u1, u2, 0.f);
        g_jU[b][j] = make_float4(u0, u1, u2, 0.f);
        g_jT[b][j] = make_float4(t0, t1, t2, oT);
        g_jS[b][j] = make_float4(s0, s1, s2, 0.f);

        float a0 = s0 - of0, a1 = s1 - of1, a2 = s2 - of2;
        float na2 = (float)((double)a0*a0 + (double)a1*a1 + (double)a2*a2);
        g_iA[b][j] = make_float4(a0, a1, a2, na2);
        g_iF[b][j] = make_float4(s0, s1, s2, 0.f);
    }
}

// ---------------------------------------------------------------------------
// rowstats: 16 rows/block. Warp = 4 rows (w&3) x j-half (w>>2, 2048 each).
// Writes cLrow = cM + log2(Srow) into BOTH g_iF.w (for k_col) and g_cL (k_out).
// ---------------------------------------------------------------------------
__global__ void __launch_bounds__(256, 4) k_rowstats() {
    __shared__ float sMin[2][16], sSum[2][16];
    int b = blockIdx.x;
    int lane = threadIdx.x & 31, w = threadIdx.x >> 5;
    int half = w >> 2;
    int rloc = (w & 3) * 4;
    int rbase = blockIdx.y * 16 + rloc;
    float4 A0 = g_iA[b][rbase+0], A1 = g_iA[b][rbase+1];
    float4 A2 = g_iA[b][rbase+2], A3 = g_iA[b][rbase+3];
    const float4* PU = &g_u4[b][half * 2048];

    float m0 = 3.4e38f, m1 = 3.4e38f, m2 = 3.4e38f, m3 = 3.4e38f;
    #pragma unroll 2
    for (int k = lane; k < 2048; k += 32) {
        float4 U = __ldg(PU + k);
        float d0 = fmaf(A0.x, U.x, fmaf(A0.y, U.y, A0.z * U.z)); m0 = fminf(m0, d0*d0);
        float d1 = fmaf(A1.x, U.x, fmaf(A1.y, U.y, A1.z * U.z)); m1 = fminf(m1, d1*d1);
        float d2 = fmaf(A2.x, U.x, fmaf(A2.y, U.y, A2.z * U.z)); m2 = fminf(m2, d2*d2);
        float d3 = fmaf(A3.x, U.x, fmaf(A3.y, U.y, A3.z * U.z)); m3 = fminf(m3, d3*d3);
    }
    m0 = wminf(m0); m1 = wminf(m1); m2 = wminf(m2); m3 = wminf(m3);
    if (lane == 0) {
        sMin[half][rloc+0] = m0; sMin[half][rloc+1] = m1;
        sMin[half][rloc+2] = m2; sMin[half][rloc+3] = m3;
    }
    __syncthreads();
    float cM0 = sqapx(fmaxf(A0.w - fminf(sMin[0][rloc+0], sMin[1][rloc+0]), 0.f)) * C50F;
    float cM1 = sqapx(fmaxf(A1.w - fminf(sMin[0][rloc+1], sMin[1][rloc+1]), 0.f)) * C50F;
    float cM2 = sqapx(fmaxf(A2.w - fminf(sMin[0][rloc+2], sMin[1][rloc+2]), 0.f)) * C50F;
    float cM3 = sqapx(fmaxf(A3.w - fminf(sMin[0][rloc+3], sMin[1][rloc+3]), 0.f)) * C50F;

    float s0 = 0.f, s1 = 0.f, s2 = 0.f, s3 = 0.f;
    for (int k = lane; k < 2048; k += 32) {
        float4 U = __ldg(PU + k);
        float d0 = fmaf(A0.x, U.x, fmaf(A0.y, U.y, A0.z * U.z));
        s0 += ex2f(fmaf(sqapx(fmaxf(fmaf(-d0, d0, A0.w), 0.f)), C50F, -cM0));
        float d1 = fmaf(A1.x, U.x, fmaf(A1.y, U.y, A1.z * U.z));
        s1 += ex2f(fmaf(sqapx(fmaxf(fmaf(-d1, d1, A1.w), 0.f)), C50F, -cM1));
        float d2 = fmaf(A2.x, U.x, fmaf(A2.y, U.y, A2.z * U.z));
        s2 += ex2f(fmaf(sqapx(fmaxf(fmaf(-d2, d2, A2.w), 0.f)), C50F, -cM2));
        float d3 = fmaf(A3.x, U.x, fmaf(A3.y, U.y, A3.z * U.z));
        s3 += ex2f(fmaf(sqapx(fmaxf(fmaf(-d3, d3, A3.w), 0.f)), C50F, -cM3));
    }
    s0 = wsumf(s0); s1 = wsumf(s1); s2 = wsumf(s2); s3 = wsumf(s3);
    if (lane == 0) {
        sSum[half][rloc+0] = s0; sSum[half][rloc+1] = s1;
        sSum[half][rloc+2] = s2; sSum[half][rloc+3] = s3;
    }
    __syncthreads();
    if (threadIdx.x < 16) {
        int r = threadIdx.x;
        int row = blockIdx.y * 16 + r;
        float m = fminf(sMin[0][r], sMin[1][r]);
        float cM = sqapx(fmaxf(g_iA[b][row].w - m, 0.f)) * C50F;
        float cL = cM + log2f(sSum[0][r] + sSum[1][r]);
        ((float*)&g_iF[b][row])[3] = cL;
        g_cL[b][row] = cL;
    }
}

// ---------------------------------------------------------------------------
// col: 16 cols/block. Warp = 4 cols (w&3) x i-half (w>>2).
// Loads A (float4) + F (float4, fs+cL); a2 = F.T. -> LSEcol2.
// ---------------------------------------------------------------------------
__global__ void __launch_bounds__(256, 4) k_col() {
    __shared__ float sSum[2][16];
    int b = blockIdx.x;
    int lane = threadIdx.x & 31, w = threadIdx.x >> 5;
    int half = w >> 2;
    int cloc = (w & 3) * 4;
    int cbase = blockIdx.y * 16 + cloc;
    float4 U0 = g_jU[b][cbase+0], U1 = g_jU[b][cbase+1];
    float4 U2 = g_jU[b][cbase+2], U3 = g_jU[b][cbase+3];
    float4 T0 = g_jT[b][cbase+0], T1 = g_jT[b][cbase+1];
    float4 T2 = g_jT[b][cbase+2], T3 = g_jT[b][cbase+3];
    const float4* PA = &g_iA[b][half * 2048];
    const float4* PF = &g_iF[b][half * 2048];

    float c0 = 0.f, c1 = 0.f, c2 = 0.f, c3 = 0.f;
    for (int k = lane; k < 2048; k += 32) {
        float4 A = __ldg(PA + k);
        float4 F = __ldg(PF + k);
        float nL = -F.w;
        float d0 = fmaf(A.x, U0.x, fmaf(A.y, U0.y, A.z * U0.z));
        float e0 = ex2f(fmaf(sqapx(fmaxf(fmaf(-d0, d0, A.w), 0.f)), C50F, nL));
        float a0 = fmaf(F.x, T0.x, fmaf(F.y, T0.y, F.z * T0.z));
        c0 += ex2f(fmaf(-a0, e0, a0));
        float d1 = fmaf(A.x, U1.x, fmaf(A.y, U1.y, A.z * U1.z));
        float e1 = ex2f(fmaf(sqapx(fmaxf(fmaf(-d1, d1, A.w), 0.f)), C50F, nL));
        float a1 = fmaf(F.x, T1.x, fmaf(F.y, T1.y, F.z * T1.z));
        c1 += ex2f(fmaf(-a1, e1, a1));
        float d2 = fmaf(A.x, U2.x, fmaf(A.y, U2.y, A.z * U2.z));
        float e2 = ex2f(fmaf(sqapx(fmaxf(fmaf(-d2, d2, A.w), 0.f)), C50F, nL));
        float a2 = fmaf(F.x, T2.x, fmaf(F.y, T2.y, F.z * T2.z));
        c2 += ex2f(fmaf(-a2, e2, a2));
        float d3 = fmaf(A.x, U3.x, fmaf(A.y, U3.y, A.z * U3.z));
        float e3 = ex2f(fmaf(sqapx(fmaxf(fmaf(-d3, d3, A.w), 0.f)), C50F, nL));
        float a3 = fmaf(F.x, T3.x, fmaf(F.y, T3.y, F.z * T3.z));
        c3 += ex2f(fmaf(-a3, e3, a3));
    }
    c0 = wsumf(c0); c1 = wsumf(c1); c2 = wsumf(c2); c3 = wsumf(c3);
    if (lane == 0) {
        sSum[half][cloc+0] = c0; sSum[half][cloc+1] = c1;
        sSum[half][cloc+2] = c2; sSum[half][cloc+3] = c3;
    }
    __syncthreads();
    if (threadIdx.x < 16) {
        int c = threadIdx.x;
        int col = blockIdx.y * 16 + c;
        float S = sSum[0][c] + sSum[1][c];
        ((float*)&g_jU[b][col])[3] = log2f(S);        // LSEcol2
    }
}

// ---------------------------------------------------------------------------
// out: 8 rows/block, warp = 4 rows (w&1) x j-quarter (w>>1).
// NO launch_bounds: let ptxas take ~72-84 regs and software-pipeline the
// three load streams past the sqrt->ex2->ex2 chain (R2 evidence: issue 54%).
// ---------------------------------------------------------------------------
__global__ void k_out(float* __restrict__ out) {
    __shared__ float sO[4][8][3];
    int b = blockIdx.x;
    int lane = threadIdx.x & 31, w = threadIdx.x >> 5;
    int rg = w & 1;
    int sp = w >> 1;
    int rbase = blockIdx.y * 8 + rg * 4;
    float4 A0 = g_iA[b][rbase+0], A1 = g_iA[b][rbase+1];
    float4 A2 = g_iA[b][rbase+2], A3 = g_iA[b][rbase+3];
    float nL0 = -g_cL[b][rbase+0], nL1 = -g_cL[b][rbase+1];
    float nL2 = -g_cL[b][rbase+2], nL3 = -g_cL[b][rbase+3];
    const float4* PU = &g_jU[b][sp * 1024];
    const float4* PT = &g_jT[b][sp * 1024];
    const float4* PS = &g_jS[b][sp * 1024];

    float x0=0,y0=0,z0=0, x1=0,y1=0,z1=0, x2=0,y2=0,z2=0, x3=0,y3=0,z3=0;
    #pragma unroll 2
    for (int k = lane; k < 1024; k += 32) {
        float4 U = __ldg(PU + k);
        float4 T = __ldg(PT + k);
        float4 S = __ldg(PS + k);
        float d0 = fmaf(A0.x, U.x, fmaf(A0.y, U.y, A0.z * U.z));
        float e0 = ex2f(fmaf(sqapx(fmaxf(fmaf(-d0, d0, A0.w), 0.f)), C50F, nL0));
        float a0 = fmaf(A0.x, T.x, fmaf(A0.y, T.y, fmaf(A0.z, T.z, T.w)));
        float p0 = ex2f(fmaf(-a0, e0, a0 - U.w));
        x0 = fmaf(p0, S.x, x0); y0 = fmaf(p0, S.y, y0); z0 = fmaf(p0, S.z, z0);
        float d1 = fmaf(A1.x, U.x, fmaf(A1.y, U.y, A1.z * U.z));
        float e1 = ex2f(fmaf(sqapx(fmaxf(fmaf(-d1, d1, A1.w), 0.f)), C50F, nL1));
        float a1 = fmaf(A1.x, T.x, fmaf(A1.y, T.y, fmaf(A1.z, T.z, T.w)));
        float p1 = ex2f(fmaf(-a1, e1, a1 - U.w));
        x1 = fmaf(p1, S.x, x1); y1 = fmaf(p1, S.y, y1); z1 = fmaf(p1, S.z, z1);
        float d2 = fmaf(A2.x, U.x, fmaf(A2.y, U.y, A2.z * U.z));
        float e2 = ex2f(fmaf(sqapx(fmaxf(fmaf(-d2, d2, A2.w), 0.f)), C50F, nL2));
        float a2 = fmaf(A2.x, T.x, fmaf(A2.y, T.y, fmaf(A2.z, T.z, T.w)));
        float p2 = ex2f(fmaf(-a2, e2, a2 - U.w));
        x2 = fmaf(p2, S.x, x2); y2 = fmaf(p2, S.y, y2); z2 = fmaf(p2, S.z, z2);
        float d3 = fmaf(A3.x, U.x, fmaf(A3.y, U.y, A3.z * U.z));
        float e3 = ex2f(fmaf(sqapx(fmaxf(fmaf(-d3, d3, A3.w), 0.f)), C50F, nL3));
        float a3 = fmaf(A3.x, T.x, fmaf(A3.y, T.y, fmaf(A3.z, T.z, T.w)));
        float p3 = ex2f(fmaf(-a3, e3, a3 - U.w));
        x3 = fmaf(p3, S.x, x3); y3 = fmaf(p3, S.y, y3); z3 = fmaf(p3, S.z, z3);
    }
    x0 = wsumf(x0); y0 = wsumf(y0); z0 = wsumf(z0);
    x1 = wsumf(x1); y1 = wsumf(y1); z1 = wsumf(z1);
    x2 = wsumf(x2); y2 = wsumf(y2); z2 = wsumf(z2);
    x3 = wsumf(x3); y3 = wsumf(y3); z3 = wsumf(z3);
    if (lane == 0) {
        int r = rg * 4;
        sO[sp][r+0][0] = x0; sO[sp][r+0][1] = y0; sO[sp][r+0][2] = z0;
        sO[sp][r+1][0] = x1; sO[sp][r+1][1] = y1; sO[sp][r+1][2] = z1;
        sO[sp][r+2][0] = x2; sO[sp][r+2][1] = y2; sO[sp][r+2][2] = z2;
        sO[sp][r+3][0] = x3; sO[sp][r+3][1] = y3; sO[sp][r+3][2] = z3;
    }
    __syncthreads();
    if (threadIdx.x < 24) {
        int r = threadIdx.x / 3, ch = threadIdx.x % 3;
        float v = sO[0][r][ch] + sO[1][r][ch] + sO[2][r][ch] + sO[3][r][ch];
        out[b * NPIX * 3 + (blockIdx.y * 8 + r) * 3 + ch] = v;
    }
}

// ---------------------------------------------------------------------------
extern "C" void kernel_launch(void* const* d_in, const int* in_sizes, int n_in,
                              void* d_out, int out_size) {
    const float* f_tar = (const float*)d_in[0];
    const float* f_src = (const float*)d_in[1];
    const float* Km    = (const float*)d_in[2];
    const float* Rm    = (const float*)d_in[3];
    const float* tv    = (const float*)d_in[4];
    float* out = (float*)d_out;

    k_pre     <<<dim3(BT, 16), 256>>>(f_tar, f_src, Km, Rm, tv);
    k_rowstats<<<dim3(BT, NPIX/16), 256>>>();
    k_col     <<<dim3(BT, NPIX/16), 256>>>();
    k_out     <<<dim3(BT, NPIX/8),  256>>>(out);
}